// round 1
// baseline (speedup 1.0000x reference)
#include <cuda_runtime.h>
#include <cuda_bf16.h>

// LIF neuron forward: T=8 timesteps, N = B*C*H*W = 32*128*32*32 = 4,194,304
// elements per timestep. Per-element serial scan over t:
//   mem = 0.5f * (mem + x[t]);          // leaky integrate, tau = 0.5
//   spike = (mem - 0.5f > 0) ? 1 : 0;   // threshold 0.5
//   mem = spike ? 0 : mem;              // reset-to-zero
// Output: spike[t][i], float32, same layout as input (T*N elements).
//
// Pure streaming kernel: 128 MB in + 128 MB out, zero reuse -> HBM-bound.
// Strategy: float4 vectorization (16B LDG/STG), all 8 timestep loads are
// address-independent so the compiler front-batches them (MLP=8/thread),
// hiding DRAM latency; the dependent FMA chain is trivial.

#define T_STEPS 8
#define N_ELEMS (32 * 128 * 32 * 32)          // elements per timestep
#define N_VEC   (N_ELEMS / 4)                 // float4 slots per timestep

__global__ __launch_bounds__(256) void lif_forward_kernel(
    const float4* __restrict__ x, float4* __restrict__ out)
{
    const int i = blockIdx.x * blockDim.x + threadIdx.x;
    if (i >= N_VEC) return;

    // Front-batch all 8 timestep loads (independent addresses -> MLP=8).
    float4 xt[T_STEPS];
#pragma unroll
    for (int t = 0; t < T_STEPS; ++t) {
        xt[t] = x[t * N_VEC + i];
    }

    float4 mem = make_float4(0.f, 0.f, 0.f, 0.f);

#pragma unroll
    for (int t = 0; t < T_STEPS; ++t) {
        // leaky integrate: mem += (x - mem) * 0.5  ==  mem = 0.5*(mem + x)
        mem.x = 0.5f * (mem.x + xt[t].x);
        mem.y = 0.5f * (mem.y + xt[t].y);
        mem.z = 0.5f * (mem.z + xt[t].z);
        mem.w = 0.5f * (mem.w + xt[t].w);

        // spike = heaviside(mem - 0.5)
        float4 sp;
        sp.x = (mem.x > 0.5f) ? 1.0f : 0.0f;
        sp.y = (mem.y > 0.5f) ? 1.0f : 0.0f;
        sp.z = (mem.z > 0.5f) ? 1.0f : 0.0f;
        sp.w = (mem.w > 0.5f) ? 1.0f : 0.0f;

        out[t * N_VEC + i] = sp;

        // reset-to-zero on spike
        mem.x = (sp.x != 0.0f) ? 0.0f : mem.x;
        mem.y = (sp.y != 0.0f) ? 0.0f : mem.y;
        mem.z = (sp.z != 0.0f) ? 0.0f : mem.z;
        mem.w = (sp.w != 0.0f) ? 0.0f : mem.w;
    }
}

extern "C" void kernel_launch(void* const* d_in, const int* in_sizes, int n_in,
                              void* d_out, int out_size)
{
    const float4* x = (const float4*)d_in[0];
    float4* out = (float4*)d_out;

    const int threads = 256;
    const int blocks = (N_VEC + threads - 1) / threads;  // 4096
    lif_forward_kernel<<<blocks, threads>>>(x, out);
}